// round 2
// baseline (speedup 1.0000x reference)
#include <cuda_runtime.h>
#include <cuda_bf16.h>

// ---------------------------------------------------------------------------
// CagnetSAGE: 2-layer GraphSAGE, N=100k, E=1.6M, D=128.
// Plan: build CSR (by dst) per call -> warp-per-node mean aggregation (no
// float atomics) -> fused dual-GEMM (K=256 concat of [agg|self]) per layer.
// ---------------------------------------------------------------------------

#define MAXN 100000
#define MAXE 1600000
#define D 128

__device__ int   g_deg[MAXN];
__device__ int   g_rowptr[MAXN];
__device__ int   g_cursor[MAXN];
__device__ int   g_col[MAXE];
__device__ float g_agg[MAXN * D];
__device__ float g_h1[MAXN * D];
__device__ float g_B1[2 * D * D];   // [256][128] row-major: concat(Wn1^T, Ws1^T)
__device__ float g_B2[2 * D * D];
__device__ float g_bias1[D];
__device__ float g_bias2[D];

// --------------------------- CSR construction ------------------------------

__global__ void zero_kernel(int n) {
    int i = blockIdx.x * blockDim.x + threadIdx.x;
    if (i < n) g_deg[i] = 0;
}

__global__ void count_kernel(const int* __restrict__ ei, int e) {
    int i = blockIdx.x * blockDim.x + threadIdx.x;
    if (i < e) {
        int dst = ei[e + i];   // edge_index row 1
        atomicAdd(&g_deg[dst], 1);
    }
}

// single-block exclusive scan of g_deg -> g_rowptr (+ g_cursor copy)
__global__ void scan_kernel(int n) {
    __shared__ int wsum[32];
    int tid = threadIdx.x, lane = tid & 31, wid = tid >> 5;
    int carry = 0;
    for (int base = 0; base < n; base += 1024) {
        int i = base + tid;
        int v = (i < n) ? g_deg[i] : 0;
        int incl = v;
        #pragma unroll
        for (int off = 1; off < 32; off <<= 1) {
            int t = __shfl_up_sync(0xffffffffu, incl, off);
            if (lane >= off) incl += t;
        }
        if (lane == 31) wsum[wid] = incl;
        __syncthreads();
        if (wid == 0) {
            int s = wsum[lane];
            #pragma unroll
            for (int off = 1; off < 32; off <<= 1) {
                int t = __shfl_up_sync(0xffffffffu, s, off);
                if (lane >= off) s += t;
            }
            wsum[lane] = s;
        }
        __syncthreads();
        int woff = (wid > 0) ? wsum[wid - 1] : 0;
        int excl = carry + woff + incl - v;
        if (i < n) { g_rowptr[i] = excl; g_cursor[i] = excl; }
        carry += wsum[31];
        __syncthreads();
    }
}

__global__ void fill_kernel(const int* __restrict__ ei, int e) {
    int i = blockIdx.x * blockDim.x + threadIdx.x;
    if (i < e) {
        int src = ei[i];
        int dst = ei[e + i];
        int pos = atomicAdd(&g_cursor[dst], 1);
        g_col[pos] = src;
    }
}

// ------------------------ weight prep (concat + transpose) -----------------
// g_B[k*128 + j] = k<128 ? Wn[j][k] : Ws[j][k-128]; bias = bn + bs
__global__ void prep_kernel(const float* __restrict__ Wn1, const float* __restrict__ Ws1,
                            const float* __restrict__ bn1, const float* __restrict__ bs1,
                            const float* __restrict__ Wn2, const float* __restrict__ Ws2,
                            const float* __restrict__ bn2, const float* __restrict__ bs2) {
    int idx = blockIdx.x * blockDim.x + threadIdx.x;
    if (idx < 2 * D * D) {
        int k = idx / D, j = idx % D;
        g_B1[idx] = (k < D) ? Wn1[j * D + k] : Ws1[j * D + (k - D)];
        g_B2[idx] = (k < D) ? Wn2[j * D + k] : Ws2[j * D + (k - D)];
    }
    if (idx < D) {
        g_bias1[idx] = bn1[idx] + bs1[idx];
        g_bias2[idx] = bn2[idx] + bs2[idx];
    }
}

// --------------------------- mean aggregation ------------------------------
// one warp per node, 4 floats (1 float4) per lane, register accumulation
__global__ void agg_kernel(const float* __restrict__ x, int n, int layer) {
    const float* feat = layer ? g_h1 : x;
    int warp = (blockIdx.x * blockDim.x + threadIdx.x) >> 5;
    int lane = threadIdx.x & 31;
    if (warp >= n) return;
    int start = g_rowptr[warp];
    int d = g_deg[warp];
    const float4* f4 = (const float4*)feat;
    float4 acc = make_float4(0.f, 0.f, 0.f, 0.f);
    int j = 0;
    // unroll-by-2 to expose load MLP
    for (; j + 1 < d; j += 2) {
        int s0 = g_col[start + j];
        int s1 = g_col[start + j + 1];
        float4 v0 = f4[(size_t)s0 * 32 + lane];
        float4 v1 = f4[(size_t)s1 * 32 + lane];
        acc.x += v0.x + v1.x;
        acc.y += v0.y + v1.y;
        acc.z += v0.z + v1.z;
        acc.w += v0.w + v1.w;
    }
    if (j < d) {
        int s0 = g_col[start + j];
        float4 v0 = f4[(size_t)s0 * 32 + lane];
        acc.x += v0.x; acc.y += v0.y; acc.z += v0.z; acc.w += v0.w;
    }
    float inv = 1.0f / (float)max(d, 1);
    acc.x *= inv; acc.y *= inv; acc.z *= inv; acc.w *= inv;
    ((float4*)g_agg)[(size_t)warp * 32 + lane] = acc;
}

// ---------------------- fused dual GEMM (K=256 concat) ---------------------
// C[n,128] = relu?( [g_agg | Aself][n,256] @ B[256,128] + bias )
__global__ __launch_bounds__(256) void gemm_dual(const float* __restrict__ x,
                                                 float* __restrict__ Cext,
                                                 int n, int layer) {
    const float* Aagg  = g_agg;
    const float* Aself = layer ? g_h1 : x;
    const float* B     = layer ? g_B2 : g_B1;
    const float* bias  = layer ? g_bias2 : g_bias1;
    float*       C     = layer ? Cext : g_h1;
    const int do_relu  = (layer == 0);

    __shared__ float As[16][128];
    __shared__ float Bs[16][128];

    int tid = threadIdx.x;
    int tx = tid & 15;       // output-col group (8 cols each)
    int ty = tid >> 4;       // output-row group (8 rows each)
    int m0 = blockIdx.x * 128;

    float acc[8][8];
    #pragma unroll
    for (int i = 0; i < 8; ++i)
        #pragma unroll
        for (int jj = 0; jj < 8; ++jj) acc[i][jj] = 0.f;

    for (int kt = 0; kt < 16; ++kt) {
        int k0 = kt * 16;
        const float* A = (k0 < D) ? Aagg : Aself;
        int kb = k0 & (D - 1);
        // load A tile transposed: As[kk][row]
        #pragma unroll
        for (int l = 0; l < 2; ++l) {
            int lin = tid + l * 256;
            int row = lin >> 2, c4 = lin & 3;
            int m = m0 + row;
            float4 v = make_float4(0.f, 0.f, 0.f, 0.f);
            if (m < n) v = *(const float4*)&A[(size_t)m * D + kb + c4 * 4];
            As[c4 * 4 + 0][row] = v.x;
            As[c4 * 4 + 1][row] = v.y;
            As[c4 * 4 + 2][row] = v.z;
            As[c4 * 4 + 3][row] = v.w;
        }
        // load B tile: Bs[kk][j]
        #pragma unroll
        for (int l = 0; l < 2; ++l) {
            int lin = tid + l * 256;
            int kk = lin >> 5, j4 = lin & 31;
            *(float4*)&Bs[kk][j4 * 4] = *(const float4*)&B[(size_t)(k0 + kk) * D + j4 * 4];
        }
        __syncthreads();
        #pragma unroll
        for (int kk = 0; kk < 16; ++kk) {
            float a[8], b[8];
            *(float4*)&a[0] = *(const float4*)&As[kk][ty * 8];
            *(float4*)&a[4] = *(const float4*)&As[kk][ty * 8 + 4];
            *(float4*)&b[0] = *(const float4*)&Bs[kk][tx * 8];
            *(float4*)&b[4] = *(const float4*)&Bs[kk][tx * 8 + 4];
            #pragma unroll
            for (int i = 0; i < 8; ++i)
                #pragma unroll
                for (int jj = 0; jj < 8; ++jj)
                    acc[i][jj] += a[i] * b[jj];
        }
        __syncthreads();
    }

    #pragma unroll
    for (int i = 0; i < 8; ++i) {
        int m = m0 + ty * 8 + i;
        if (m >= n) continue;
        #pragma unroll
        for (int jj = 0; jj < 8; jj += 4) {
            int col = tx * 8 + jj;
            float4 v;
            v.x = acc[i][jj + 0] + bias[col + 0];
            v.y = acc[i][jj + 1] + bias[col + 1];
            v.z = acc[i][jj + 2] + bias[col + 2];
            v.w = acc[i][jj + 3] + bias[col + 3];
            if (do_relu) {
                v.x = fmaxf(v.x, 0.f); v.y = fmaxf(v.y, 0.f);
                v.z = fmaxf(v.z, 0.f); v.w = fmaxf(v.w, 0.f);
            }
            *(float4*)&C[(size_t)m * D + col] = v;
        }
    }
}

// ---------------------------------------------------------------------------

extern "C" void kernel_launch(void* const* d_in, const int* in_sizes, int n_in,
                              void* d_out, int out_size) {
    const float* x   = (const float*)d_in[0];
    const int*   ei  = (const int*)d_in[1];
    const float* Wn1 = (const float*)d_in[2];
    const float* bn1 = (const float*)d_in[3];
    const float* Ws1 = (const float*)d_in[4];
    const float* bs1 = (const float*)d_in[5];
    const float* Wn2 = (const float*)d_in[6];
    const float* bn2 = (const float*)d_in[7];
    const float* Ws2 = (const float*)d_in[8];
    const float* bs2 = (const float*)d_in[9];
    float* out = (float*)d_out;

    int n = in_sizes[0] / D;
    int e = in_sizes[1] / 2;
    if (n > MAXN) n = MAXN;
    if (e > MAXE) e = MAXE;

    // CSR build
    zero_kernel <<<(n + 255) / 256, 256>>>(n);
    count_kernel<<<(e + 255) / 256, 256>>>(ei, e);
    scan_kernel <<<1, 1024>>>(n);
    fill_kernel <<<(e + 255) / 256, 256>>>(ei, e);
    // weight prep
    prep_kernel <<<(2 * D * D + 255) / 256, 256>>>(Wn1, Ws1, bn1, bs1, Wn2, Ws2, bn2, bs2);

    int agg_blocks  = (n + 7) / 8;          // 8 warps/block
    int gemm_blocks = (n + 127) / 128;

    // layer 1
    agg_kernel<<<agg_blocks, 256>>>(x, n, 0);
    gemm_dual <<<gemm_blocks, 256>>>(x, out, n, 0);
    // layer 2
    agg_kernel<<<agg_blocks, 256>>>(x, n, 1);
    gemm_dual <<<gemm_blocks, 256>>>(x, out, n, 1);
}

// round 4
// speedup vs baseline: 1.4347x; 1.4347x over previous
#include <cuda_runtime.h>
#include <cuda_bf16.h>
#include <cstdint>

// ---------------------------------------------------------------------------
// CagnetSAGE: 2-layer GraphSAGE, N=100k, E=1.6M, D=128.
// CSR build -> warp-per-node mean aggregation -> mma.sync bf16 split GEMM
// (K=256 concat of [agg|self], A/B split into bf16 hi+lo, 3 products).
// NOTE: tcgen05 is unavailable (harness PTX stage targets plain sm_103);
// using base-ISA ldmatrix + mma.sync.m16n8k16.bf16.
// ---------------------------------------------------------------------------

#define MAXN 100000
#define MAXE 1600000
#define DF 128

__device__ int   g_deg[MAXN];
__device__ int   g_rowptr[MAXN];
__device__ int   g_cursor[MAXN];
__device__ int   g_col[MAXE];
__device__ float g_agg[MAXN * DF];
__device__ float g_h1[MAXN * DF];
// Pre-swizzled SMEM image of B (N=128 x K=256), atom-blocked:
// off = (k>>6)*16384 + n*128 + (k&63)*2, XOR SW128. hi then lo (32768 bf16 each).
__device__ __nv_bfloat16 g_Bimg[2][65536];
__device__ float g_bias1[DF];
__device__ float g_bias2[DF];

// --------------------------- helpers ---------------------------------------

__device__ __forceinline__ uint32_t smem_u32(const void* p) {
    uint32_t a;
    asm("{ .reg .u64 t; cvta.to.shared.u64 t, %1; cvt.u32.u64 %0, t; }"
        : "=r"(a) : "l"(p));
    return a;
}

__device__ __forceinline__ uint32_t sw128(uint32_t off) {
    return off ^ ((off >> 3) & 0x70u);
}

__device__ __forceinline__ void ldm_x4(uint32_t addr, uint32_t& r0, uint32_t& r1,
                                       uint32_t& r2, uint32_t& r3) {
    asm volatile("ldmatrix.sync.aligned.m8n8.x4.shared.b16 {%0,%1,%2,%3}, [%4];"
                 : "=r"(r0), "=r"(r1), "=r"(r2), "=r"(r3) : "r"(addr));
}

__device__ __forceinline__ void mma_bf16(float* c, const uint32_t* a, uint32_t b0, uint32_t b1) {
    asm volatile(
        "mma.sync.aligned.m16n8k16.row.col.f32.bf16.bf16.f32 "
        "{%0,%1,%2,%3}, {%4,%5,%6,%7}, {%8,%9}, {%0,%1,%2,%3};"
        : "+f"(c[0]), "+f"(c[1]), "+f"(c[2]), "+f"(c[3])
        : "r"(a[0]), "r"(a[1]), "r"(a[2]), "r"(a[3]), "r"(b0), "r"(b1));
}

// --------------------------- CSR construction ------------------------------

__global__ void zero_kernel(int n) {
    int i = blockIdx.x * blockDim.x + threadIdx.x;
    if (i < n) g_deg[i] = 0;
}

__global__ void count_kernel(const int* __restrict__ ei, int e) {
    int i = blockIdx.x * blockDim.x + threadIdx.x;
    if (i < e) atomicAdd(&g_deg[ei[e + i]], 1);
}

__global__ void scan_kernel(int n) {
    __shared__ int wsum[32];
    int tid = threadIdx.x, lane = tid & 31, wid = tid >> 5;
    int carry = 0;
    for (int base = 0; base < n; base += 1024) {
        int i = base + tid;
        int v = (i < n) ? g_deg[i] : 0;
        int incl = v;
        #pragma unroll
        for (int off = 1; off < 32; off <<= 1) {
            int t = __shfl_up_sync(0xffffffffu, incl, off);
            if (lane >= off) incl += t;
        }
        if (lane == 31) wsum[wid] = incl;
        __syncthreads();
        if (wid == 0) {
            int s = wsum[lane];
            #pragma unroll
            for (int off = 1; off < 32; off <<= 1) {
                int t = __shfl_up_sync(0xffffffffu, s, off);
                if (lane >= off) s += t;
            }
            wsum[lane] = s;
        }
        __syncthreads();
        int woff = (wid > 0) ? wsum[wid - 1] : 0;
        int excl = carry + woff + incl - v;
        if (i < n) { g_rowptr[i] = excl; g_cursor[i] = excl; }
        carry += wsum[31];
        __syncthreads();
    }
}

__global__ void fill_kernel(const int* __restrict__ ei, int e) {
    int i = blockIdx.x * blockDim.x + threadIdx.x;
    if (i < e) {
        int src = ei[i];
        int dst = ei[e + i];
        int pos = atomicAdd(&g_cursor[dst], 1);
        g_col[pos] = src;
    }
}

// ------------------------ weight prep: split + swizzle ---------------------

__global__ void prep_kernel(const float* __restrict__ Wn1, const float* __restrict__ Ws1,
                            const float* __restrict__ bn1, const float* __restrict__ bs1,
                            const float* __restrict__ Wn2, const float* __restrict__ Ws2,
                            const float* __restrict__ bn2, const float* __restrict__ bs2) {
    int idx = blockIdx.x * blockDim.x + threadIdx.x;
    if (idx < 2 * 128 * 256) {
        int layer = idx >> 15;
        int r = idx & 32767;
        int nrow = r >> 8;          // 0..127 (output feature j)
        int k = r & 255;            // 0..255 (concat K)
        const float* Wn = layer ? Wn2 : Wn1;
        const float* Ws = layer ? Ws2 : Ws1;
        float w = (k < 128) ? Wn[nrow * 128 + k] : Ws[nrow * 128 + (k - 128)];
        __nv_bfloat16 h = __float2bfloat16_rn(w);
        __nv_bfloat16 l = __float2bfloat16_rn(w - __bfloat162float(h));
        uint32_t off = (uint32_t)(k >> 6) * 16384u + (uint32_t)nrow * 128u
                     + (uint32_t)(k & 63) * 2u;
        uint32_t sw = sw128(off);
        g_Bimg[layer][sw >> 1]           = h;
        g_Bimg[layer][32768 + (sw >> 1)] = l;
    }
    if (idx < 128) {
        g_bias1[idx] = bn1[idx] + bs1[idx];
        g_bias2[idx] = bn2[idx] + bs2[idx];
    }
}

// --------------------------- mean aggregation ------------------------------

__global__ void agg_kernel(const float* __restrict__ x, int n, int layer) {
    const float* feat = layer ? g_h1 : x;
    int warp = (blockIdx.x * blockDim.x + threadIdx.x) >> 5;
    int lane = threadIdx.x & 31;
    if (warp >= n) return;
    int start = g_rowptr[warp];
    int d = g_deg[warp];
    const float4* f4 = (const float4*)feat;
    float4 acc = make_float4(0.f, 0.f, 0.f, 0.f);
    int j = 0;
    for (; j + 1 < d; j += 2) {
        int s0 = g_col[start + j];
        int s1 = g_col[start + j + 1];
        float4 v0 = f4[(size_t)s0 * 32 + lane];
        float4 v1 = f4[(size_t)s1 * 32 + lane];
        acc.x += v0.x + v1.x; acc.y += v0.y + v1.y;
        acc.z += v0.z + v1.z; acc.w += v0.w + v1.w;
    }
    if (j < d) {
        int s0 = g_col[start + j];
        float4 v0 = f4[(size_t)s0 * 32 + lane];
        acc.x += v0.x; acc.y += v0.y; acc.z += v0.z; acc.w += v0.w;
    }
    float inv = 1.0f / (float)max(d, 1);
    acc.x *= inv; acc.y *= inv; acc.z *= inv; acc.w *= inv;
    ((float4*)g_agg)[(size_t)warp * 32 + lane] = acc;
}

// ---------------------- mma.sync split-bf16 GEMM ---------------------------
// C[n,128] = relu?( [g_agg | Aself][n,256] @ B[256,128] + bias )
// Block tile 128x128, 8 warps (warp tile 32x64), K in 4 chunks of 64.

#define SM_B      0          // B hi [0,64K), B lo [64K,128K)
#define SM_A      131072     // 2 bufs x (hi 16KB + lo 16KB)
#define SM_BIAS   196608
#define SMEM_TOTAL 197120

union Pk { uint4 q; __nv_bfloat162 h[4]; };

__device__ __forceinline__ void split_pack(float4 u, float4 v, uint4& hi, uint4& lo) {
    float f[8] = {u.x, u.y, u.z, u.w, v.x, v.y, v.z, v.w};
    Pk H, L;
    #pragma unroll
    for (int i = 0; i < 4; ++i) {
        __nv_bfloat16 h0 = __float2bfloat16_rn(f[2 * i]);
        __nv_bfloat16 h1 = __float2bfloat16_rn(f[2 * i + 1]);
        float l0 = f[2 * i]     - __bfloat162float(h0);
        float l1 = f[2 * i + 1] - __bfloat162float(h1);
        H.h[i] = __halves2bfloat162(h0, h1);
        L.h[i] = __halves2bfloat162(__float2bfloat16_rn(l0), __float2bfloat16_rn(l1));
    }
    hi = H.q; lo = L.q;
}

__global__ __launch_bounds__(256, 1)
void gemm_tc(const float* __restrict__ x, float* __restrict__ out, int n, int layer) {
    extern __shared__ char smem[];
    const int tid = threadIdx.x;
    const int wid = tid >> 5;
    const int lane = tid & 31;
    uint32_t sbase = smem_u32(smem);

    const float* Aagg  = g_agg;
    const float* Aself = layer ? g_h1 : x;
    const float* bias  = layer ? g_bias2 : g_bias1;
    float*       C     = layer ? out : g_h1;
    const int m0 = blockIdx.x * 128;
    const int do_relu = (layer == 0);

    // copy pre-swizzled B image (hi+lo, 128KB)
    {
        const uint4* src = (const uint4*)&g_Bimg[layer][0];
        uint4* dst = (uint4*)smem;
        #pragma unroll 8
        for (int i = tid; i < 8192; i += 256) dst[i] = src[i];
    }
    if (tid < 128) ((float*)(smem + SM_BIAS))[tid] = bias[tid];

    const int warp_m = (wid & 3) * 32;
    const int warp_n = (wid >> 2) * 64;
    const int seg = lane >> 3;   // 0..3
    const int lr  = lane & 7;

    float acc[2][8][4];
    #pragma unroll
    for (int mt = 0; mt < 2; ++mt)
        #pragma unroll
        for (int nt = 0; nt < 8; ++nt)
            #pragma unroll
            for (int q = 0; q < 4; ++q) acc[mt][nt][q] = 0.f;

    // staging coords for this thread
    const int rS    = tid >> 1;
    const int halfS = tid & 1;
    const int mS    = min(m0 + rS, n - 1);

    for (int kc = 0; kc < 4; ++kc) {
        const int b = kc & 1;
        char* Ah = smem + SM_A + b * 32768;
        char* Al = Ah + 16384;

        // stage chunk kc (64 K-cols) into buffer b
        {
            const float* src = (kc < 2) ? Aagg : Aself;
            const int kb = (kc & 1) * 64;
            const float4* s4 = (const float4*)(src + (size_t)mS * 128 + kb + halfS * 32);
            #pragma unroll
            for (int g = 0; g < 4; ++g) {
                float4 u = s4[2 * g], v = s4[2 * g + 1];
                uint4 hq, lq;
                split_pack(u, v, hq, lq);
                uint32_t off = sw128((uint32_t)rS * 128u + (uint32_t)halfS * 64u
                                     + (uint32_t)g * 16u);
                *(uint4*)(Ah + off) = hq;
                *(uint4*)(Al + off) = lq;
            }
        }
        __syncthreads();

        const uint32_t aH = sbase + SM_A + b * 32768;
        const uint32_t bH = sbase + kc * 16384;

        #pragma unroll
        for (int ks = 0; ks < 4; ++ks) {
            // A fragments: 2 m-tiles, hi + lo
            uint32_t fAh[2][4], fAl[2][4];
            #pragma unroll
            for (int mt = 0; mt < 2; ++mt) {
                int row = warp_m + mt * 16 + (seg & 1) * 8 + lr;
                int kcol = ks * 16 + (seg >> 1) * 8;
                uint32_t off = sw128((uint32_t)row * 128u + (uint32_t)kcol * 2u);
                ldm_x4(aH + off, fAh[mt][0], fAh[mt][1], fAh[mt][2], fAh[mt][3]);
                ldm_x4(aH + 16384 + off, fAl[mt][0], fAl[mt][1], fAl[mt][2], fAl[mt][3]);
            }
            // B fragments per 2-ntile group
            #pragma unroll
            for (int g = 0; g < 4; ++g) {
                int row = warp_n + g * 16 + (seg >> 1) * 8 + lr;
                int kcol = ks * 16 + (seg & 1) * 8;
                uint32_t off = sw128((uint32_t)row * 128u + (uint32_t)kcol * 2u);
                uint32_t bh0, bh1, bh2, bh3, bl0, bl1, bl2, bl3;
                ldm_x4(bH + off, bh0, bh1, bh2, bh3);
                ldm_x4(bH + 65536 + off, bl0, bl1, bl2, bl3);
                #pragma unroll
                for (int mt = 0; mt < 2; ++mt) {
                    mma_bf16(acc[mt][2 * g],     fAh[mt], bh0, bh1);
                    mma_bf16(acc[mt][2 * g + 1], fAh[mt], bh2, bh3);
                    mma_bf16(acc[mt][2 * g],     fAh[mt], bl0, bl1);
                    mma_bf16(acc[mt][2 * g + 1], fAh[mt], bl2, bl3);
                    mma_bf16(acc[mt][2 * g],     fAl[mt], bh0, bh1);
                    mma_bf16(acc[mt][2 * g + 1], fAl[mt], bh2, bh3);
                }
            }
        }
    }

    // epilogue: c frag layout — lane l: rows l/4, l/4+8; cols (l%4)*2, +1
    const float* sb = (const float*)(smem + SM_BIAS);
    #pragma unroll
    for (int mt = 0; mt < 2; ++mt) {
        int r0 = m0 + warp_m + mt * 16 + (lane >> 2);
        #pragma unroll
        for (int nt = 0; nt < 8; ++nt) {
            int col = warp_n + nt * 8 + (lane & 3) * 2;
            float b0 = sb[col], b1 = sb[col + 1];
            float2 v0, v1;
            v0.x = acc[mt][nt][0] + b0; v0.y = acc[mt][nt][1] + b1;
            v1.x = acc[mt][nt][2] + b0; v1.y = acc[mt][nt][3] + b1;
            if (do_relu) {
                v0.x = fmaxf(v0.x, 0.f); v0.y = fmaxf(v0.y, 0.f);
                v1.x = fmaxf(v1.x, 0.f); v1.y = fmaxf(v1.y, 0.f);
            }
            if (r0 < n)     *(float2*)&C[(size_t)r0 * 128 + col] = v0;
            if (r0 + 8 < n) *(float2*)&C[(size_t)(r0 + 8) * 128 + col] = v1;
        }
    }
}

// ---------------------------------------------------------------------------

extern "C" void kernel_launch(void* const* d_in, const int* in_sizes, int n_in,
                              void* d_out, int out_size) {
    const float* x   = (const float*)d_in[0];
    const int*   ei  = (const int*)d_in[1];
    const float* Wn1 = (const float*)d_in[2];
    const float* bn1 = (const float*)d_in[3];
    const float* Ws1 = (const float*)d_in[4];
    const float* bs1 = (const float*)d_in[5];
    const float* Wn2 = (const float*)d_in[6];
    const float* bn2 = (const float*)d_in[7];
    const float* Ws2 = (const float*)d_in[8];
    const float* bs2 = (const float*)d_in[9];
    float* out = (float*)d_out;

    int n = in_sizes[0] / DF;
    int e = in_sizes[1] / 2;
    if (n > MAXN) n = MAXN;
    if (e > MAXE) e = MAXE;

    cudaFuncSetAttribute(gemm_tc, cudaFuncAttributeMaxDynamicSharedMemorySize, SMEM_TOTAL);

    // CSR build
    zero_kernel <<<(n + 255) / 256, 256>>>(n);
    count_kernel<<<(e + 255) / 256, 256>>>(ei, e);
    scan_kernel <<<1, 1024>>>(n);
    fill_kernel <<<(e + 255) / 256, 256>>>(ei, e);
    // weight prep (split + swizzle image + bias fuse)
    prep_kernel <<<(2 * 128 * 256 + 255) / 256, 256>>>(Wn1, Ws1, bn1, bs1,
                                                       Wn2, Ws2, bn2, bs2);

    int agg_blocks  = (n + 7) / 8;
    int gemm_blocks = (n + 127) / 128;

    agg_kernel<<<agg_blocks, 256>>>(x, n, 0);
    gemm_tc   <<<gemm_blocks, 256, SMEM_TOTAL>>>(x, out, n, 0);
    agg_kernel<<<agg_blocks, 256>>>(x, n, 1);
    gemm_tc   <<<gemm_blocks, 256, SMEM_TOTAL>>>(x, out, n, 1);
}

// round 5
// speedup vs baseline: 1.6931x; 1.1801x over previous
#include <cuda_runtime.h>
#include <cuda_bf16.h>
#include <cuda_fp16.h>
#include <cstdint>

// ---------------------------------------------------------------------------
// CagnetSAGE: 2-layer GraphSAGE, N=100k, E=1.6M, D=128.
// CSR build (ILP-4 atomics, 3-phase scan) -> fp16-gather mean aggregation ->
// mma.sync bf16 hi/lo split GEMM (K=256 concat of [agg|self]).
// ---------------------------------------------------------------------------

#define MAXN 100000
#define MAXE 1600000
#define DF 128

__device__ int   g_deg[MAXN];
__device__ int   g_rowptr[MAXN];
__device__ int   g_cursor[MAXN];
__device__ int   g_bsum[128];
__device__ int   g_col[MAXE];
__device__ float g_agg[MAXN * DF];
__device__ float g_h1[MAXN * DF];
__device__ __half g_feath[MAXN * DF];   // fp16 gather copy: x (layer1), h1 (layer2)
// Pre-swizzled SMEM image of B (N=128 x K=256), atom-blocked:
// off = (k>>6)*16384 + n*128 + (k&63)*2, XOR SW128. hi then lo (32768 bf16 each).
__device__ __nv_bfloat16 g_Bimg[2][65536];
__device__ float g_bias1[DF];
__device__ float g_bias2[DF];

// --------------------------- helpers ---------------------------------------

__device__ __forceinline__ uint32_t smem_u32(const void* p) {
    uint32_t a;
    asm("{ .reg .u64 t; cvta.to.shared.u64 t, %1; cvt.u32.u64 %0, t; }"
        : "=r"(a) : "l"(p));
    return a;
}

__device__ __forceinline__ uint32_t sw128(uint32_t off) {
    return off ^ ((off >> 3) & 0x70u);
}

__device__ __forceinline__ void ldm_x4(uint32_t addr, uint32_t& r0, uint32_t& r1,
                                       uint32_t& r2, uint32_t& r3) {
    asm volatile("ldmatrix.sync.aligned.m8n8.x4.shared.b16 {%0,%1,%2,%3}, [%4];"
                 : "=r"(r0), "=r"(r1), "=r"(r2), "=r"(r3) : "r"(addr));
}

__device__ __forceinline__ void mma_bf16(float* c, const uint32_t* a, uint32_t b0, uint32_t b1) {
    asm volatile(
        "mma.sync.aligned.m16n8k16.row.col.f32.bf16.bf16.f32 "
        "{%0,%1,%2,%3}, {%4,%5,%6,%7}, {%8,%9}, {%0,%1,%2,%3};"
        : "+f"(c[0]), "+f"(c[1]), "+f"(c[2]), "+f"(c[3])
        : "r"(a[0]), "r"(a[1]), "r"(a[2]), "r"(a[3]), "r"(b0), "r"(b1));
}

__device__ __forceinline__ int warp_incl_scan(int v, int lane) {
    #pragma unroll
    for (int off = 1; off < 32; off <<= 1) {
        int t = __shfl_up_sync(0xffffffffu, v, off);
        if (lane >= off) v += t;
    }
    return v;
}

// --------------------------- CSR construction ------------------------------

__global__ void zero_kernel(int n) {
    int i = blockIdx.x * blockDim.x + threadIdx.x;
    if (i < n) g_deg[i] = 0;
}

// 4 edges per thread (int4) for atomic MLP
__global__ void count_kernel(const int* __restrict__ ei, int e) {
    int i = blockIdx.x * blockDim.x + threadIdx.x;
    int base = i * 4;
    if (base + 3 < e) {
        int4 d = *(const int4*)(ei + e + base);
        atomicAdd(&g_deg[d.x], 1);
        atomicAdd(&g_deg[d.y], 1);
        atomicAdd(&g_deg[d.z], 1);
        atomicAdd(&g_deg[d.w], 1);
    } else {
        for (int j = base; j < e; ++j) atomicAdd(&g_deg[ei[e + j]], 1);
    }
}

// phase 1: per-block (1024) exclusive scan of g_deg -> g_rowptr, block sums
__global__ void scan1_kernel(int n) {
    __shared__ int wsum[32];
    int tid = threadIdx.x, lane = tid & 31, wid = tid >> 5;
    int i = blockIdx.x * 1024 + tid;
    int v = (i < n) ? g_deg[i] : 0;
    int incl = warp_incl_scan(v, lane);
    if (lane == 31) wsum[wid] = incl;
    __syncthreads();
    if (wid == 0) wsum[lane] = warp_incl_scan(wsum[lane], lane);
    __syncthreads();
    int woff = wid ? wsum[wid - 1] : 0;
    if (i < n) g_rowptr[i] = woff + incl - v;
    if (tid == 0) g_bsum[blockIdx.x] = wsum[31];
}

// phase 2: exclusive scan of block sums (nb <= 128) in one 128-thread block
__global__ void scan2_kernel(int nb) {
    __shared__ int ws[4];
    int tid = threadIdx.x, lane = tid & 31, wid = tid >> 5;
    int v = (tid < nb) ? g_bsum[tid] : 0;
    int incl = warp_incl_scan(v, lane);
    if (lane == 31) ws[wid] = incl;
    __syncthreads();
    if (tid == 0) {
        int r = 0;
        #pragma unroll
        for (int w = 0; w < 4; ++w) { int t = ws[w]; ws[w] = r; r += t; }
    }
    __syncthreads();
    if (tid < nb) g_bsum[tid] = ws[wid] + incl - v;
}

// phase 3: add block offsets, copy to cursor
__global__ void scan3_kernel(int n) {
    int i = blockIdx.x * blockDim.x + threadIdx.x;
    if (i < n) {
        int r = g_rowptr[i] + g_bsum[i >> 10];
        g_rowptr[i] = r;
        g_cursor[i] = r;
    }
}

__global__ void fill_kernel(const int* __restrict__ ei, int e) {
    int i = blockIdx.x * blockDim.x + threadIdx.x;
    int base = i * 4;
    if (base + 3 < e) {
        int4 s = *(const int4*)(ei + base);
        int4 d = *(const int4*)(ei + e + base);
        int p0 = atomicAdd(&g_cursor[d.x], 1);
        int p1 = atomicAdd(&g_cursor[d.y], 1);
        int p2 = atomicAdd(&g_cursor[d.z], 1);
        int p3 = atomicAdd(&g_cursor[d.w], 1);
        g_col[p0] = s.x; g_col[p1] = s.y; g_col[p2] = s.z; g_col[p3] = s.w;
    } else {
        for (int j = base; j < e; ++j) {
            int pos = atomicAdd(&g_cursor[ei[e + j]], 1);
            g_col[pos] = ei[j];
        }
    }
}

// ------------------------ weight prep: split + swizzle ---------------------

__global__ void prep_kernel(const float* __restrict__ Wn1, const float* __restrict__ Ws1,
                            const float* __restrict__ bn1, const float* __restrict__ bs1,
                            const float* __restrict__ Wn2, const float* __restrict__ Ws2,
                            const float* __restrict__ bn2, const float* __restrict__ bs2) {
    int idx = blockIdx.x * blockDim.x + threadIdx.x;
    if (idx < 2 * 128 * 256) {
        int layer = idx >> 15;
        int r = idx & 32767;
        int nrow = r >> 8;          // 0..127 (output feature j)
        int k = r & 255;            // 0..255 (concat K)
        const float* Wn = layer ? Wn2 : Wn1;
        const float* Ws = layer ? Ws2 : Ws1;
        float w = (k < 128) ? Wn[nrow * 128 + k] : Ws[nrow * 128 + (k - 128)];
        __nv_bfloat16 h = __float2bfloat16_rn(w);
        __nv_bfloat16 l = __float2bfloat16_rn(w - __bfloat162float(h));
        uint32_t off = (uint32_t)(k >> 6) * 16384u + (uint32_t)nrow * 128u
                     + (uint32_t)(k & 63) * 2u;
        uint32_t sw = sw128(off);
        g_Bimg[layer][sw >> 1]           = h;
        g_Bimg[layer][32768 + (sw >> 1)] = l;
    }
    if (idx < 128) {
        g_bias1[idx] = bn1[idx] + bs1[idx];
        g_bias2[idx] = bn2[idx] + bs2[idx];
    }
}

// ------------------------ x -> fp16 conversion -----------------------------

__global__ void convert_kernel(const float* __restrict__ x, int total4) {
    int i = blockIdx.x * blockDim.x + threadIdx.x;   // one float4 each
    if (i < total4) {
        float4 v = ((const float4*)x)[i];
        __half2 h0 = __floats2half2_rn(v.x, v.y);
        __half2 h1 = __floats2half2_rn(v.z, v.w);
        uint2 pk;
        pk.x = *(uint32_t*)&h0;
        pk.y = *(uint32_t*)&h1;
        ((uint2*)g_feath)[i] = pk;
    }
}

// --------------------------- mean aggregation ------------------------------
// warp per node; lane loads 4 halves (uint2, 8B) per src row; fp32 accum.

__global__ void agg_kernel(int n) {
    int warp = (blockIdx.x * blockDim.x + threadIdx.x) >> 5;
    int lane = threadIdx.x & 31;
    if (warp >= n) return;
    int start = g_rowptr[warp];
    int d = g_deg[warp];
    const uint2* f = (const uint2*)g_feath;   // row = 32 uint2
    float4 acc = make_float4(0.f, 0.f, 0.f, 0.f);
    int j = 0;
    for (; j + 3 < d; j += 4) {
        int s0 = g_col[start + j];
        int s1 = g_col[start + j + 1];
        int s2 = g_col[start + j + 2];
        int s3 = g_col[start + j + 3];
        uint2 v0 = f[s0 * 32 + lane];
        uint2 v1 = f[s1 * 32 + lane];
        uint2 v2 = f[s2 * 32 + lane];
        uint2 v3 = f[s3 * 32 + lane];
        #pragma unroll
        for (int q = 0; q < 4; ++q) {
            uint2 v = (q == 0) ? v0 : (q == 1) ? v1 : (q == 2) ? v2 : v3;
            float2 a = __half22float2(*(__half2*)&v.x);
            float2 b = __half22float2(*(__half2*)&v.y);
            acc.x += a.x; acc.y += a.y; acc.z += b.x; acc.w += b.y;
        }
    }
    for (; j < d; ++j) {
        int s0 = g_col[start + j];
        uint2 v = f[s0 * 32 + lane];
        float2 a = __half22float2(*(__half2*)&v.x);
        float2 b = __half22float2(*(__half2*)&v.y);
        acc.x += a.x; acc.y += a.y; acc.z += b.x; acc.w += b.y;
    }
    float inv = 1.0f / (float)max(d, 1);
    acc.x *= inv; acc.y *= inv; acc.z *= inv; acc.w *= inv;
    ((float4*)g_agg)[(size_t)warp * 32 + lane] = acc;
}

// ---------------------- mma.sync split-bf16 GEMM ---------------------------
// C[n,128] = relu?( [g_agg | Aself][n,256] @ B[256,128] + bias )
// Block tile 128x128, 8 warps (warp tile 32x64), K in 4 chunks of 64.

#define SM_B      0          // B hi [0,64K), B lo [64K,128K)
#define SM_A      131072     // 2 bufs x (hi 16KB + lo 16KB)
#define SM_BIAS   196608
#define SMEM_TOTAL 197120

union Pk { uint4 q; __nv_bfloat162 h[4]; };

__device__ __forceinline__ void split_pack(float4 u, float4 v, uint4& hi, uint4& lo) {
    float f[8] = {u.x, u.y, u.z, u.w, v.x, v.y, v.z, v.w};
    Pk H, L;
    #pragma unroll
    for (int i = 0; i < 4; ++i) {
        __nv_bfloat16 h0 = __float2bfloat16_rn(f[2 * i]);
        __nv_bfloat16 h1 = __float2bfloat16_rn(f[2 * i + 1]);
        float l0 = f[2 * i]     - __bfloat162float(h0);
        float l1 = f[2 * i + 1] - __bfloat162float(h1);
        H.h[i] = __halves2bfloat162(h0, h1);
        L.h[i] = __halves2bfloat162(__float2bfloat16_rn(l0), __float2bfloat16_rn(l1));
    }
    hi = H.q; lo = L.q;
}

__global__ __launch_bounds__(256, 1)
void gemm_tc(const float* __restrict__ x, float* __restrict__ out, int n, int layer) {
    extern __shared__ char smem[];
    const int tid = threadIdx.x;
    const int wid = tid >> 5;
    const int lane = tid & 31;
    uint32_t sbase = smem_u32(smem);

    const float* Aagg  = g_agg;
    const float* Aself = layer ? g_h1 : x;
    const float* bias  = layer ? g_bias2 : g_bias1;
    float*       C     = layer ? out : g_h1;
    const int m0 = blockIdx.x * 128;
    const int do_relu = (layer == 0);

    // copy pre-swizzled B image (hi+lo, 128KB)
    {
        const uint4* src = (const uint4*)&g_Bimg[layer][0];
        uint4* dst = (uint4*)smem;
        #pragma unroll 8
        for (int i = tid; i < 8192; i += 256) dst[i] = src[i];
    }
    if (tid < 128) ((float*)(smem + SM_BIAS))[tid] = bias[tid];

    const int warp_m = (wid & 3) * 32;
    const int warp_n = (wid >> 2) * 64;
    const int seg = lane >> 3;   // 0..3
    const int lr  = lane & 7;

    float acc[2][8][4];
    #pragma unroll
    for (int mt = 0; mt < 2; ++mt)
        #pragma unroll
        for (int nt = 0; nt < 8; ++nt)
            #pragma unroll
            for (int q = 0; q < 4; ++q) acc[mt][nt][q] = 0.f;

    // staging coords for this thread
    const int rS    = tid >> 1;
    const int halfS = tid & 1;
    const int mS    = min(m0 + rS, n - 1);

    for (int kc = 0; kc < 4; ++kc) {
        const int b = kc & 1;
        char* Ah = smem + SM_A + b * 32768;
        char* Al = Ah + 16384;

        // stage chunk kc (64 K-cols) into buffer b
        {
            const float* src = (kc < 2) ? Aagg : Aself;
            const int kb = (kc & 1) * 64;
            const float4* s4 = (const float4*)(src + (size_t)mS * 128 + kb + halfS * 32);
            #pragma unroll
            for (int g = 0; g < 4; ++g) {
                float4 u = s4[2 * g], v = s4[2 * g + 1];
                uint4 hq, lq;
                split_pack(u, v, hq, lq);
                uint32_t off = sw128((uint32_t)rS * 128u + (uint32_t)halfS * 64u
                                     + (uint32_t)g * 16u);
                *(uint4*)(Ah + off) = hq;
                *(uint4*)(Al + off) = lq;
            }
        }
        __syncthreads();

        const uint32_t aH = sbase + SM_A + b * 32768;
        const uint32_t bH = sbase + kc * 16384;

        #pragma unroll
        for (int ks = 0; ks < 4; ++ks) {
            uint32_t fAh[2][4], fAl[2][4];
            #pragma unroll
            for (int mt = 0; mt < 2; ++mt) {
                int row = warp_m + mt * 16 + (seg & 1) * 8 + lr;
                int kcol = ks * 16 + (seg >> 1) * 8;
                uint32_t off = sw128((uint32_t)row * 128u + (uint32_t)kcol * 2u);
                ldm_x4(aH + off, fAh[mt][0], fAh[mt][1], fAh[mt][2], fAh[mt][3]);
                ldm_x4(aH + 16384 + off, fAl[mt][0], fAl[mt][1], fAl[mt][2], fAl[mt][3]);
            }
            #pragma unroll
            for (int g = 0; g < 4; ++g) {
                int row = warp_n + g * 16 + (seg >> 1) * 8 + lr;
                int kcol = ks * 16 + (seg & 1) * 8;
                uint32_t off = sw128((uint32_t)row * 128u + (uint32_t)kcol * 2u);
                uint32_t bh0, bh1, bh2, bh3, bl0, bl1, bl2, bl3;
                ldm_x4(bH + off, bh0, bh1, bh2, bh3);
                ldm_x4(bH + 65536 + off, bl0, bl1, bl2, bl3);
                #pragma unroll
                for (int mt = 0; mt < 2; ++mt) {
                    mma_bf16(acc[mt][2 * g],     fAh[mt], bh0, bh1);
                    mma_bf16(acc[mt][2 * g + 1], fAh[mt], bh2, bh3);
                    mma_bf16(acc[mt][2 * g],     fAh[mt], bl0, bl1);
                    mma_bf16(acc[mt][2 * g + 1], fAh[mt], bl2, bl3);
                    mma_bf16(acc[mt][2 * g],     fAl[mt], bh0, bh1);
                    mma_bf16(acc[mt][2 * g + 1], fAl[mt], bh2, bh3);
                }
            }
        }
    }

    // epilogue: lane l -> rows l/4, l/4+8; cols (l%4)*2, +1
    const float* sb = (const float*)(smem + SM_BIAS);
    #pragma unroll
    for (int mt = 0; mt < 2; ++mt) {
        int r0 = m0 + warp_m + mt * 16 + (lane >> 2);
        #pragma unroll
        for (int nt = 0; nt < 8; ++nt) {
            int col = warp_n + nt * 8 + (lane & 3) * 2;
            float b0 = sb[col], b1 = sb[col + 1];
            float2 v0, v1;
            v0.x = acc[mt][nt][0] + b0; v0.y = acc[mt][nt][1] + b1;
            v1.x = acc[mt][nt][2] + b0; v1.y = acc[mt][nt][3] + b1;
            if (do_relu) {
                v0.x = fmaxf(v0.x, 0.f); v0.y = fmaxf(v0.y, 0.f);
                v1.x = fmaxf(v1.x, 0.f); v1.y = fmaxf(v1.y, 0.f);
            }
            if (r0 < n) {
                *(float2*)&C[(size_t)r0 * 128 + col] = v0;
                if (do_relu) {
                    __half2 h = __floats2half2_rn(v0.x, v0.y);
                    *(__half2*)&g_feath[(size_t)r0 * 128 + col] = h;
                }
            }
            if (r0 + 8 < n) {
                *(float2*)&C[(size_t)(r0 + 8) * 128 + col] = v1;
                if (do_relu) {
                    __half2 h = __floats2half2_rn(v1.x, v1.y);
                    *(__half2*)&g_feath[(size_t)(r0 + 8) * 128 + col] = h;
                }
            }
        }
    }
}

// ---------------------------------------------------------------------------

extern "C" void kernel_launch(void* const* d_in, const int* in_sizes, int n_in,
                              void* d_out, int out_size) {
    const float* x   = (const float*)d_in[0];
    const int*   ei  = (const int*)d_in[1];
    const float* Wn1 = (const float*)d_in[2];
    const float* bn1 = (const float*)d_in[3];
    const float* Ws1 = (const float*)d_in[4];
    const float* bs1 = (const float*)d_in[5];
    const float* Wn2 = (const float*)d_in[6];
    const float* bn2 = (const float*)d_in[7];
    const float* Ws2 = (const float*)d_in[8];
    const float* bs2 = (const float*)d_in[9];
    float* out = (float*)d_out;

    int n = in_sizes[0] / DF;
    int e = in_sizes[1] / 2;
    if (n > MAXN) n = MAXN;
    if (e > MAXE) e = MAXE;
    int nb = (n + 1023) / 1024;
    int e4 = (e + 3) / 4;

    cudaFuncSetAttribute(gemm_tc, cudaFuncAttributeMaxDynamicSharedMemorySize, SMEM_TOTAL);

    // CSR build
    zero_kernel  <<<(n + 255) / 256, 256>>>(n);
    count_kernel <<<(e4 + 255) / 256, 256>>>(ei, e);
    scan1_kernel <<<nb, 1024>>>(n);
    scan2_kernel <<<1, 128>>>(nb);
    scan3_kernel <<<(n + 255) / 256, 256>>>(n);
    fill_kernel  <<<(e4 + 255) / 256, 256>>>(ei, e);
    // weight prep + fp16 feature copy
    prep_kernel  <<<(2 * 128 * 256 + 255) / 256, 256>>>(Wn1, Ws1, bn1, bs1,
                                                        Wn2, Ws2, bn2, bs2);
    convert_kernel<<<(n * 32 + 255) / 256, 256>>>(x, n * 32);

    int agg_blocks  = (n + 7) / 8;
    int gemm_blocks = (n + 127) / 128;

    agg_kernel<<<agg_blocks, 256>>>(n);                       // gathers g_feath (= x)
    gemm_tc   <<<gemm_blocks, 256, SMEM_TOTAL>>>(x, out, n, 0);  // writes h1 + fp16 copy
    agg_kernel<<<agg_blocks, 256>>>(n);                       // gathers g_feath (= h1)
    gemm_tc   <<<gemm_blocks, 256, SMEM_TOTAL>>>(x, out, n, 1);
}

// round 7
// speedup vs baseline: 1.7146x; 1.0127x over previous
#include <cuda_runtime.h>
#include <cuda_bf16.h>
#include <cuda_fp16.h>
#include <cstdint>

// ---------------------------------------------------------------------------
// CagnetSAGE: 2-layer GraphSAGE, N=100k, E=1.6M, D=128.
// CSR build -> fp16-gather mean aggregation writing pre-split/pre-swizzled
// bf16 hi/lo A-images -> persistent mma.sync bf16 3-product GEMM whose A
// staging is a pure copy (no fp32 intermediates anywhere).
// A-image layout: node m, concat-k k(0..255): chunk=k>>6 (0,1=agg; 2,3=self),
// c=k&63; index = m*256 + chunk*64 + (c ^ ((m&7)<<3))  [pre-applied SW128].
// ---------------------------------------------------------------------------

#define MAXN 100000
#define MAXE 1600000
#define DF 128

__device__ int   g_deg[MAXN];
__device__ int   g_rowptr[MAXN];
__device__ int   g_cursor[MAXN];
__device__ int   g_bsum[128];
__device__ int   g_col[MAXE];
__device__ __half g_feath[MAXN * DF];          // fp16 gather copy (x then h1)
__device__ __nv_bfloat16 g_Ahi[MAXN * 256];    // A image hi (agg|self)
__device__ __nv_bfloat16 g_Alo[MAXN * 256];    // A image lo
// Pre-swizzled B image (N=128 x K=256): off=(k>>6)*16384+n*128+(k&63)*2 ^SW128
__device__ __nv_bfloat16 g_Bimg[2][65536];     // hi [0,32768), lo [32768,65536)
__device__ float g_bias1[DF];
__device__ float g_bias2[DF];

// --------------------------- helpers ---------------------------------------

__device__ __forceinline__ uint32_t smem_u32(const void* p) {
    uint32_t a;
    asm("{ .reg .u64 t; cvta.to.shared.u64 t, %1; cvt.u32.u64 %0, t; }"
        : "=r"(a) : "l"(p));
    return a;
}

__device__ __forceinline__ uint32_t sw128(uint32_t off) {
    return off ^ ((off >> 3) & 0x70u);
}

__device__ __forceinline__ void ldm_x4(uint32_t addr, uint32_t& r0, uint32_t& r1,
                                       uint32_t& r2, uint32_t& r3) {
    asm volatile("ldmatrix.sync.aligned.m8n8.x4.shared.b16 {%0,%1,%2,%3}, [%4];"
                 : "=r"(r0), "=r"(r1), "=r"(r2), "=r"(r3) : "r"(addr));
}

__device__ __forceinline__ void mma_bf16(float* c, const uint32_t* a, uint32_t b0, uint32_t b1) {
    asm volatile(
        "mma.sync.aligned.m16n8k16.row.col.f32.bf16.bf16.f32 "
        "{%0,%1,%2,%3}, {%4,%5,%6,%7}, {%8,%9}, {%0,%1,%2,%3};"
        : "+f"(c[0]), "+f"(c[1]), "+f"(c[2]), "+f"(c[3])
        : "r"(a[0]), "r"(a[1]), "r"(a[2]), "r"(a[3]), "r"(b0), "r"(b1));
}

__device__ __forceinline__ int warp_incl_scan(int v, int lane) {
    #pragma unroll
    for (int off = 1; off < 32; off <<= 1) {
        int t = __shfl_up_sync(0xffffffffu, v, off);
        if (lane >= off) v += t;
    }
    return v;
}

union BPair { uint32_t u; __nv_bfloat162 h; };

__device__ __forceinline__ uint32_t pack_hi2(float a, float b) {
    BPair p;
    p.h = __halves2bfloat162(__float2bfloat16_rn(a), __float2bfloat16_rn(b));
    return p.u;
}
__device__ __forceinline__ uint32_t pack_lo2(float a, float b) {
    float ra = a - __bfloat162float(__float2bfloat16_rn(a));
    float rb = b - __bfloat162float(__float2bfloat16_rn(b));
    BPair p;
    p.h = __halves2bfloat162(__float2bfloat16_rn(ra), __float2bfloat16_rn(rb));
    return p.u;
}

// --------------------------- setup: zero + prep + convert ------------------

__global__ void setup_kernel(const float* __restrict__ x,
                             const float* __restrict__ Wn1, const float* __restrict__ Ws1,
                             const float* __restrict__ bn1, const float* __restrict__ bs1,
                             const float* __restrict__ Wn2, const float* __restrict__ Ws2,
                             const float* __restrict__ bn2, const float* __restrict__ bs2,
                             int n) {
    int i = blockIdx.x * blockDim.x + threadIdx.x;
    int nconv = n * 32;
    if (i < nconv) {
        // convert x: float4 -> feath fp16 + self image hi/lo
        int m = i >> 5, lane = i & 31;
        float4 v = ((const float4*)x)[i];
        __half2 a = __floats2half2_rn(v.x, v.y);
        __half2 b = __floats2half2_rn(v.z, v.w);
        uint2 pk;
        pk.x = *(uint32_t*)&a;
        pk.y = *(uint32_t*)&b;
        ((uint2*)g_feath)[i] = pk;
        int chunk = 2 + (lane >> 4);
        int c = (lane * 4) & 63;
        int idx = m * 256 + chunk * 64 + (c ^ ((m & 7) << 3));
        uint2 hq, lq;
        hq.x = pack_hi2(v.x, v.y); hq.y = pack_hi2(v.z, v.w);
        lq.x = pack_lo2(v.x, v.y); lq.y = pack_lo2(v.z, v.w);
        *(uint2*)&g_Ahi[idx] = hq;
        *(uint2*)&g_Alo[idx] = lq;
    } else if (i < nconv + 65536) {
        // weight prep: split + swizzle B image
        int r = i - nconv;
        int layer = r >> 15;
        int rr = r & 32767;
        int nrow = rr >> 8;
        int k = rr & 255;
        const float* Wn = layer ? Wn2 : Wn1;
        const float* Ws = layer ? Ws2 : Ws1;
        float w = (k < 128) ? Wn[nrow * 128 + k] : Ws[nrow * 128 + (k - 128)];
        __nv_bfloat16 h = __float2bfloat16_rn(w);
        __nv_bfloat16 l = __float2bfloat16_rn(w - __bfloat162float(h));
        uint32_t off = (uint32_t)(k >> 6) * 16384u + (uint32_t)nrow * 128u
                     + (uint32_t)(k & 63) * 2u;
        uint32_t sw = sw128(off);
        g_Bimg[layer][sw >> 1]           = h;
        g_Bimg[layer][32768 + (sw >> 1)] = l;
    } else if (i < nconv + 65536 + 128) {
        int b = i - nconv - 65536;
        g_bias1[b] = bn1[b] + bs1[b];
        g_bias2[b] = bn2[b] + bs2[b];
    } else if (i < nconv + 65536 + 128 + n) {
        g_deg[i - nconv - 65536 - 128] = 0;
    }
}

// --------------------------- CSR construction ------------------------------

__global__ void count_kernel(const int* __restrict__ ei, int e) {
    int i = blockIdx.x * blockDim.x + threadIdx.x;
    int base = i * 4;
    if (base + 3 < e) {
        int4 d = *(const int4*)(ei + e + base);
        atomicAdd(&g_deg[d.x], 1);
        atomicAdd(&g_deg[d.y], 1);
        atomicAdd(&g_deg[d.z], 1);
        atomicAdd(&g_deg[d.w], 1);
    } else {
        for (int j = base; j < e; ++j) atomicAdd(&g_deg[ei[e + j]], 1);
    }
}

__global__ void scan1_kernel(int n) {
    __shared__ int wsum[32];
    int tid = threadIdx.x, lane = tid & 31, wid = tid >> 5;
    int i = blockIdx.x * 1024 + tid;
    int v = (i < n) ? g_deg[i] : 0;
    int incl = warp_incl_scan(v, lane);
    if (lane == 31) wsum[wid] = incl;
    __syncthreads();
    if (wid == 0) wsum[lane] = warp_incl_scan(wsum[lane], lane);
    __syncthreads();
    int woff = wid ? wsum[wid - 1] : 0;
    if (i < n) g_rowptr[i] = woff + incl - v;
    if (tid == 0) g_bsum[blockIdx.x] = wsum[31];
}

__global__ void scan2_kernel(int nb) {
    __shared__ int ws[4];
    int tid = threadIdx.x, lane = tid & 31, wid = tid >> 5;
    int v = (tid < nb) ? g_bsum[tid] : 0;
    int incl = warp_incl_scan(v, lane);
    if (lane == 31) ws[wid] = incl;
    __syncthreads();
    if (tid == 0) {
        int r = 0;
        #pragma unroll
        for (int w = 0; w < 4; ++w) { int t = ws[w]; ws[w] = r; r += t; }
    }
    __syncthreads();
    if (tid < nb) g_bsum[tid] = ws[wid] + incl - v;
}

__global__ void scan3_kernel(int n) {
    int i = blockIdx.x * blockDim.x + threadIdx.x;
    if (i < n) {
        int r = g_rowptr[i] + g_bsum[i >> 10];
        g_rowptr[i] = r;
        g_cursor[i] = r;
    }
}

__global__ void fill_kernel(const int* __restrict__ ei, int e) {
    int i = blockIdx.x * blockDim.x + threadIdx.x;
    int base = i * 4;
    if (base + 3 < e) {
        int4 s = *(const int4*)(ei + base);
        int4 d = *(const int4*)(ei + e + base);
        int p0 = atomicAdd(&g_cursor[d.x], 1);
        int p1 = atomicAdd(&g_cursor[d.y], 1);
        int p2 = atomicAdd(&g_cursor[d.z], 1);
        int p3 = atomicAdd(&g_cursor[d.w], 1);
        g_col[p0] = s.x; g_col[p1] = s.y; g_col[p2] = s.z; g_col[p3] = s.w;
    } else {
        for (int j = base; j < e; ++j) {
            int pos = atomicAdd(&g_cursor[ei[e + j]], 1);
            g_col[pos] = ei[j];
        }
    }
}

// --------------------------- mean aggregation ------------------------------
// warp per node; lane loads 4 halves (uint2) per src row; fp32 accum;
// writes split bf16 hi/lo directly into the pre-swizzled A image (agg part).

__global__ void agg_kernel(int n) {
    int warp = (blockIdx.x * blockDim.x + threadIdx.x) >> 5;
    int lane = threadIdx.x & 31;
    if (warp >= n) return;
    int start = g_rowptr[warp];
    int d = g_deg[warp];
    const uint2* f = (const uint2*)g_feath;
    float4 acc = make_float4(0.f, 0.f, 0.f, 0.f);
    int j = 0;
    for (; j + 3 < d; j += 4) {
        int s0 = g_col[start + j];
        int s1 = g_col[start + j + 1];
        int s2 = g_col[start + j + 2];
        int s3 = g_col[start + j + 3];
        uint2 v0 = f[s0 * 32 + lane];
        uint2 v1 = f[s1 * 32 + lane];
        uint2 v2 = f[s2 * 32 + lane];
        uint2 v3 = f[s3 * 32 + lane];
        #pragma unroll
        for (int q = 0; q < 4; ++q) {
            uint2 v = (q == 0) ? v0 : (q == 1) ? v1 : (q == 2) ? v2 : v3;
            float2 a = __half22float2(*(__half2*)&v.x);
            float2 b = __half22float2(*(__half2*)&v.y);
            acc.x += a.x; acc.y += a.y; acc.z += b.x; acc.w += b.y;
        }
    }
    for (; j < d; ++j) {
        int s0 = g_col[start + j];
        uint2 v = f[s0 * 32 + lane];
        float2 a = __half22float2(*(__half2*)&v.x);
        float2 b = __half22float2(*(__half2*)&v.y);
        acc.x += a.x; acc.y += a.y; acc.z += b.x; acc.w += b.y;
    }
    float inv = 1.0f / (float)max(d, 1);
    acc.x *= inv; acc.y *= inv; acc.z *= inv; acc.w *= inv;

    int chunk = lane >> 4;               // 0 or 1 (agg part)
    int c = (lane * 4) & 63;
    int idx = warp * 256 + chunk * 64 + (c ^ ((warp & 7) << 3));
    uint2 hq, lq;
    hq.x = pack_hi2(acc.x, acc.y); hq.y = pack_hi2(acc.z, acc.w);
    lq.x = pack_lo2(acc.x, acc.y); lq.y = pack_lo2(acc.z, acc.w);
    *(uint2*)&g_Ahi[idx] = hq;
    *(uint2*)&g_Alo[idx] = lq;
}

// ---------------------- persistent mma.sync split-bf16 GEMM ----------------
// C[n,128] = relu?( A[n,256] @ B[256,128] + bias ), A from hi/lo images.
// Block tile 128x128, 8 warps (warp tile 32x64), K in 4 chunks of 64.
// Persistent: B + bias loaded once; tiles strided by gridDim.

#define SM_B      0          // B hi [0,64K), B lo [64K,128K)
#define SM_A      131072     // 2 bufs x (hi 16KB + lo 16KB)
#define SM_BIAS   196608
#define SMEM_TOTAL 197120

__global__ __launch_bounds__(256, 1)
void gemm_tc(float* __restrict__ out, int n, int layer) {
    extern __shared__ char smem[];
    const int tid = threadIdx.x;
    const int wid = tid >> 5;
    const int lane = tid & 31;
    uint32_t sbase = smem_u32(smem);

    const float* bias = layer ? g_bias2 : g_bias1;
    const int do_relu = (layer == 0);

    // copy pre-swizzled B image (hi+lo, 128KB) once
    {
        const uint4* src = (const uint4*)&g_Bimg[layer][0];
        uint4* dst = (uint4*)smem;
        #pragma unroll 8
        for (int i = tid; i < 8192; i += 256) dst[i] = src[i];
    }
    if (tid < 128) ((float*)(smem + SM_BIAS))[tid] = bias[tid];

    const int warp_m = (wid & 3) * 32;
    const int warp_n = (wid >> 2) * 64;
    const int seg = lane >> 3;
    const int lr  = lane & 7;
    const int rS  = tid >> 1;       // staging row
    const int qS  = tid & 1;        // staging half (64B)
    const float* sb = (const float*)(smem + SM_BIAS);

    const int tiles = (n + 127) / 128;

    for (int t = blockIdx.x; t < tiles; t += gridDim.x) {
        const int m0 = t * 128;
        const int mS = min(m0 + rS, n - 1);

        float acc[2][8][4];
        #pragma unroll
        for (int mt = 0; mt < 2; ++mt)
            #pragma unroll
            for (int nt = 0; nt < 8; ++nt)
                #pragma unroll
                for (int q = 0; q < 4; ++q) acc[mt][nt][q] = 0.f;

        for (int kc = 0; kc < 4; ++kc) {
            const int b = kc & 1;
            char* Ah = smem + SM_A + b * 32768;
            char* Al = Ah + 16384;

            // pure-copy staging: 128B/row from pre-swizzled images
            {
                const uint4* sh = (const uint4*)(g_Ahi + (size_t)mS * 256 + kc * 64) + qS * 4;
                const uint4* sl = (const uint4*)(g_Alo + (size_t)mS * 256 + kc * 64) + qS * 4;
                uint4* dh = (uint4*)(Ah + rS * 128 + qS * 64);
                uint4* dl = (uint4*)(Al + rS * 128 + qS * 64);
                #pragma unroll
                for (int i = 0; i < 4; ++i) { dh[i] = sh[i]; dl[i] = sl[i]; }
            }
            __syncthreads();

            const uint32_t aH = sbase + SM_A + b * 32768;
            const uint32_t bH = sbase + kc * 16384;

            #pragma unroll
            for (int ks = 0; ks < 4; ++ks) {
                uint32_t fAh[2][4], fAl[2][4];
                #pragma unroll
                for (int mt = 0; mt < 2; ++mt) {
                    int row = warp_m + mt * 16 + (seg & 1) * 8 + lr;
                    int kcol = ks * 16 + (seg >> 1) * 8;
                    uint32_t off = sw128((uint32_t)row * 128u + (uint32_t)kcol * 2u);
                    ldm_x4(aH + off, fAh[mt][0], fAh[mt][1], fAh[mt][2], fAh[mt][3]);
                    ldm_x4(aH + 16384 + off, fAl[mt][0], fAl[mt][1], fAl[mt][2], fAl[mt][3]);
                }
                #pragma unroll
                for (int g = 0; g < 4; ++g) {
                    int row = warp_n + g * 16 + (seg >> 1) * 8 + lr;
                    int kcol = ks * 16 + (seg & 1) * 8;
                    uint32_t off = sw128((uint32_t)row * 128u + (uint32_t)kcol * 2u);
                    uint32_t bh0, bh1, bh2, bh3, bl0, bl1, bl2, bl3;
                    ldm_x4(bH + off, bh0, bh1, bh2, bh3);
                    ldm_x4(bH + 65536 + off, bl0, bl1, bl2, bl3);
                    #pragma unroll
                    for (int mt = 0; mt < 2; ++mt) {
                        mma_bf16(acc[mt][2 * g],     fAh[mt], bh0, bh1);
                        mma_bf16(acc[mt][2 * g + 1], fAh[mt], bh2, bh3);
                        mma_bf16(acc[mt][2 * g],     fAh[mt], bl0, bl1);
                        mma_bf16(acc[mt][2 * g + 1], fAh[mt], bl2, bl3);
                        mma_bf16(acc[mt][2 * g],     fAl[mt], bh0, bh1);
                        mma_bf16(acc[mt][2 * g + 1], fAl[mt], bh2, bh3);
                    }
                }
            }
        }

        // epilogue: lane l -> rows l/4, l/4+8; cols (l%4)*2, +1
        #pragma unroll
        for (int mt = 0; mt < 2; ++mt) {
            int rbase = m0 + warp_m + mt * 16 + (lane >> 2);
            #pragma unroll
            for (int nt = 0; nt < 8; ++nt) {
                int col = warp_n + nt * 8 + (lane & 3) * 2;
                float b0 = sb[col], b1 = sb[col + 1];
                float2 v0, v1;
                v0.x = acc[mt][nt][0] + b0; v0.y = acc[mt][nt][1] + b1;
                v1.x = acc[mt][nt][2] + b0; v1.y = acc[mt][nt][3] + b1;
                if (do_relu) {
                    v0.x = fmaxf(v0.x, 0.f); v0.y = fmaxf(v0.y, 0.f);
                    v1.x = fmaxf(v1.x, 0.f); v1.y = fmaxf(v1.y, 0.f);
                }
                #pragma unroll
                for (int h = 0; h < 2; ++h) {
                    int mm = rbase + h * 8;
                    if (mm >= n) continue;
                    float2 v = h ? v1 : v0;
                    if (layer == 0) {
                        // h1 -> fp16 gather copy + self image hi/lo
                        __half2 ph = __floats2half2_rn(v.x, v.y);
                        *(__half2*)&g_feath[(size_t)mm * 128 + col] = ph;
                        int chunk = 2 + (col >> 6);
                        int c = col & 63;
                        int idx = mm * 256 + chunk * 64 + (c ^ ((mm & 7) << 3));
                        *(uint32_t*)&g_Ahi[idx] = pack_hi2(v.x, v.y);
                        *(uint32_t*)&g_Alo[idx] = pack_lo2(v.x, v.y);
                    } else {
                        *(float2*)&out[(size_t)mm * 128 + col] = v;
                    }
                }
            }
        }
    }
}

// ---------------------------------------------------------------------------

extern "C" void kernel_launch(void* const* d_in, const int* in_sizes, int n_in,
                              void* d_out, int out_size) {
    const float* x   = (const float*)d_in[0];
    const int*   ei  = (const int*)d_in[1];
    const float* Wn1 = (const float*)d_in[2];
    const float* bn1 = (const float*)d_in[3];
    const float* Ws1 = (const float*)d_in[4];
    const float* bs1 = (const float*)d_in[5];
    const float* Wn2 = (const float*)d_in[6];
    const float* bn2 = (const float*)d_in[7];
    const float* Ws2 = (const float*)d_in[8];
    const float* bs2 = (const float*)d_in[9];
    float* out = (float*)d_out;

    int n = in_sizes[0] / DF;
    int e = in_sizes[1] / 2;
    if (n > MAXN) n = MAXN;
    if (e > MAXE) e = MAXE;
    int nb = (n + 1023) / 1024;
    int e4 = (e + 3) / 4;
    int setup_total = n * 32 + 65536 + 128 + n;

    cudaFuncSetAttribute(gemm_tc, cudaFuncAttributeMaxDynamicSharedMemorySize, SMEM_TOTAL);

    setup_kernel <<<(setup_total + 255) / 256, 256>>>(x, Wn1, Ws1, bn1, bs1,
                                                      Wn2, Ws2, bn2, bs2, n);
    count_kernel <<<(e4 + 255) / 256, 256>>>(ei, e);
    scan1_kernel <<<nb, 1024>>>(n);
    scan2_kernel <<<1, 128>>>(nb);
    scan3_kernel <<<(n + 255) / 256, 256>>>(n);
    fill_kernel  <<<(e4 + 255) / 256, 256>>>(ei, e);

    int agg_blocks = (n + 7) / 8;
    int tiles = (n + 127) / 128;
    int gemm_grid = tiles < 148 ? tiles : 148;

    agg_kernel<<<agg_blocks, 256>>>(n);                    // agg(x) -> images
    gemm_tc   <<<gemm_grid, 256, SMEM_TOTAL>>>(out, n, 0); // h1 -> feath + images
    agg_kernel<<<agg_blocks, 256>>>(n);                    // agg(h1) -> images
    gemm_tc   <<<gemm_grid, 256, SMEM_TOTAL>>>(out, n, 1);
}